// round 2
// baseline (speedup 1.0000x reference)
#include <cuda_runtime.h>
#include <cstdint>
#include <cstddef>

// Problem constants
#define B_  256
#define T_  512
#define I_  64
#define H_  256
#define G_  1024            // 4*H
#define BT_ (B_ * T_)       // 131072

// -------- scratch (device globals; no allocation allowed) --------
__device__ float g_xp[(size_t)BT_ * G_];   // 512 MB: gate pre-activations for current layer
__device__ float g_s0[(size_t)BT_ * H_];   // 128 MB: layer output sequence (ping)
__device__ float g_s1[(size_t)BT_ * H_];   // 128 MB: layer output sequence (pong)

// =====================================================================
// GEMM: C[M,N] = A[M,K] * B[N,K]^T + bias1[N] (+ bias2[N])
// Both A and B are K-contiguous (row-major [*,K]) -> symmetric loads.
// BM=128, BN=64, BK=16, 256 threads, 8x4 thread tile.
// =====================================================================
__global__ void __launch_bounds__(256, 2)
gemm_abt_bias(const float* __restrict__ A, const float* __restrict__ Bm,
              const float* __restrict__ bias1, const float* __restrict__ bias2,
              float* __restrict__ C, int M, int N, int K)
{
    __shared__ float As[16][128];
    __shared__ float Bs[16][64];

    const int tid = threadIdx.x;
    const int m0  = blockIdx.y * 128;
    const int n0  = blockIdx.x * 64;
    const int ty8 = (tid >> 4) * 8;   // row offset within tile (0..120)
    const int tx4 = (tid & 15) * 4;   // col offset within tile (0..60)

    float acc[8][4] = {};

    const int ntile = K >> 4;
    for (int kt = 0; kt < ntile; ++kt) {
        const int k0 = kt << 4;
        // Load A tile 128x16 (transposed into As[k][m])
#pragma unroll
        for (int r = 0; r < 2; ++r) {
            int idx = tid + (r << 8);
            int m = idx >> 2, kq = idx & 3;
            float4 v = *(const float4*)&A[(size_t)(m0 + m) * K + k0 + (kq << 2)];
            As[kq * 4 + 0][m] = v.x; As[kq * 4 + 1][m] = v.y;
            As[kq * 4 + 2][m] = v.z; As[kq * 4 + 3][m] = v.w;
        }
        // Load B tile 64x16 (transposed into Bs[k][n])
        {
            int n = tid >> 2, kq = tid & 3;
            float4 v = *(const float4*)&Bm[(size_t)(n0 + n) * K + k0 + (kq << 2)];
            Bs[kq * 4 + 0][n] = v.x; Bs[kq * 4 + 1][n] = v.y;
            Bs[kq * 4 + 2][n] = v.z; Bs[kq * 4 + 3][n] = v.w;
        }
        __syncthreads();

#pragma unroll
        for (int kk = 0; kk < 16; ++kk) {
            float4 a0 = *(const float4*)&As[kk][ty8];
            float4 a1 = *(const float4*)&As[kk][ty8 + 4];
            float4 bv = *(const float4*)&Bs[kk][tx4];
            float ar[8] = {a0.x, a0.y, a0.z, a0.w, a1.x, a1.y, a1.z, a1.w};
            float br[4] = {bv.x, bv.y, bv.z, bv.w};
#pragma unroll
            for (int i = 0; i < 8; ++i)
#pragma unroll
                for (int j = 0; j < 4; ++j)
                    acc[i][j] += ar[i] * br[j];
        }
        __syncthreads();
    }

    float bvv[4];
#pragma unroll
    for (int j = 0; j < 4; ++j) {
        float b = bias1[n0 + tx4 + j];
        if (bias2) b += bias2[n0 + tx4 + j];
        bvv[j] = b;
    }
#pragma unroll
    for (int i = 0; i < 8; ++i) {
        float4 o;
        o.x = acc[i][0] + bvv[0]; o.y = acc[i][1] + bvv[1];
        o.z = acc[i][2] + bvv[2]; o.w = acc[i][3] + bvv[3];
        *(float4*)&C[(size_t)(m0 + ty8 + i) * N + n0 + tx4] = o;
    }
}

// =====================================================================
// Recurrent LSTM scan (one layer), cluster-of-8 persistent kernel.
//   grid = 128 CTAs = 16 clusters x 8.
//   Cluster cb owns batch rows [cb*16, cb*16+16) for all T steps.
//   CTA rank r owns hidden cols [r*32, r*32+32), i.e. gate rows
//   {g*256 + r*32 + c : g in 0..3, c in 0..31} of Whh -> 128x256 fp32
//   slice resident in SMEM (pitch 260 floats -> 4-bank lane stride,
//   conflict-free for LDS.128 8-lane phases).
//   Per step: stage full h_prev (16x256) from global (L2), GEMM from
//   SMEM, gate math fully in registers (thread owns all 4 gates of one
//   hidden col for 2 batch rows), write h to seq_out, cluster barrier
//   (release/acquire makes peers' h visible).
// =====================================================================
#define WP 260
#define REC_SMEM ((128 * WP + 16 * WP) * 4)

__device__ __forceinline__ float fsig(float x) {
    x = fminf(fmaxf(x, -30.f), 30.f);
    return __fdividef(1.f, 1.f + __expf(-x));
}
__device__ __forceinline__ float ftanh_(float x) {
    x = fminf(fmaxf(x, -15.f), 15.f);
    float e = __expf(-2.f * x);
    return __fdividef(1.f - e, 1.f + e);
}

__global__ void __cluster_dims__(8, 1, 1) __launch_bounds__(256, 1)
lstm_rec(const float* __restrict__ Whh, const float* __restrict__ xp,
         float* __restrict__ seq_out)
{
    extern __shared__ float sm[];
    float* Ws = sm;              // [128][WP]
    float* hb = sm + 128 * WP;   // [16][WP]

    const int tid  = threadIdx.x;
    const int rank = blockIdx.x & 7;
    const int b0   = (blockIdx.x >> 3) * 16;

    // Load this CTA's Whh slice: Ws[g*32+c][k] = Whh[g*256 + rank*32 + c][k]
    for (int idx = tid; idx < 128 * 64; idx += 256) {
        int row = idx >> 6, q = idx & 63;
        int gr  = ((row >> 5) << 8) + (rank << 5) + (row & 31);
        float4 v = *(const float4*)&Whh[(size_t)gr * H_ + (q << 2)];
        *(float4*)&Ws[row * WP + (q << 2)] = v;
    }

    const int w  = tid >> 5, l = tid & 31;
    const int bA = b0 + 2 * w, bB = bA + 1;
    const int hc = (rank << 5) + l;

    const float* xpA = xp + (size_t)bA * T_ * G_ + hc;
    const float* xpB = xp + (size_t)bB * T_ * G_ + hc;
    float* soA = seq_out + (size_t)bA * T_ * H_ + hc;
    float* soB = seq_out + (size_t)bB * T_ * H_ + hc;

    const float* hA  = &hb[(2 * w) * WP];
    const float* hBp = &hb[(2 * w + 1) * WP];

    float cA = 0.f, cB = 0.f;
    __syncthreads();

    for (int t = 0; t < T_; ++t) {
        // Prefetch gate pre-activations for this step (independent of h)
        float xv[2][4];
#pragma unroll
        for (int j = 0; j < 4; ++j) {
            xv[0][j] = __ldg(&xpA[(size_t)t * G_ + (j << 8)]);
            xv[1][j] = __ldg(&xpB[(size_t)t * G_ + (j << 8)]);
        }

        // Stage h_{t-1} (full 16x256) into SMEM
        if (t == 0) {
#pragma unroll
            for (int jj = 0; jj < 4; ++jj) {
                int idx = tid + (jj << 8);
                int b = idx >> 6, q = idx & 63;
                *(float4*)&hb[b * WP + (q << 2)] = make_float4(0.f, 0.f, 0.f, 0.f);
            }
        } else {
#pragma unroll
            for (int jj = 0; jj < 4; ++jj) {
                int idx = tid + (jj << 8);
                int b = idx >> 6, q = idx & 63;
                float4 v = *(const float4*)&seq_out[((size_t)(b0 + b) * T_ + (t - 1)) * H_ + (q << 2)];
                *(float4*)&hb[b * WP + (q << 2)] = v;
            }
        }
        __syncthreads();

        // GEMM: acc[b][g] = sum_k h[b][k] * Ws[l + 32g][k]
        float acc[2][4] = {};
#pragma unroll 4
        for (int kq = 0; kq < 64; ++kq) {
            float4 ha  = *(const float4*)&hA[kq << 2];
            float4 hbv = *(const float4*)&hBp[kq << 2];
#pragma unroll
            for (int j = 0; j < 4; ++j) {
                float4 wv = *(const float4*)&Ws[(l + (j << 5)) * WP + (kq << 2)];
                acc[0][j] += ha.x * wv.x;  acc[0][j] += ha.y * wv.y;
                acc[0][j] += ha.z * wv.z;  acc[0][j] += ha.w * wv.w;
                acc[1][j] += hbv.x * wv.x; acc[1][j] += hbv.y * wv.y;
                acc[1][j] += hbv.z * wv.z; acc[1][j] += hbv.w * wv.w;
            }
        }

        // Gates (i, f, g, o) -> c, h   (all register-local)
        {
            float ig = fsig (acc[0][0] + xv[0][0]);
            float fg = fsig (acc[0][1] + xv[0][1]);
            float gg = ftanh_(acc[0][2] + xv[0][2]);
            float og = fsig (acc[0][3] + xv[0][3]);
            cA = fg * cA + ig * gg;
            soA[(size_t)t * H_] = og * ftanh_(cA);
        }
        {
            float ig = fsig (acc[1][0] + xv[1][0]);
            float fg = fsig (acc[1][1] + xv[1][1]);
            float gg = ftanh_(acc[1][2] + xv[1][2]);
            float og = fsig (acc[1][3] + xv[1][3]);
            cB = fg * cB + ig * gg;
            soB[(size_t)t * H_] = og * ftanh_(cB);
        }

        // Cluster barrier: release h writes, acquire peers' h for next step.
        asm volatile("barrier.cluster.arrive.aligned;\n\t"
                     "barrier.cluster.wait.aligned;\n\t" ::: "memory");
    }
}

// =====================================================================
// Launcher
// =====================================================================
extern "C" void kernel_launch(void* const* d_in, const int* in_sizes, int n_in,
                              void* d_out, int out_size)
{
    const float* x        = (const float*)d_in[0];
    const float* eWih0    = (const float*)d_in[1];
    const float* eWhh0    = (const float*)d_in[2];
    const float* ebih0    = (const float*)d_in[3];
    const float* ebhh0    = (const float*)d_in[4];
    const float* eWih1    = (const float*)d_in[5];
    const float* eWhh1    = (const float*)d_in[6];
    const float* ebih1    = (const float*)d_in[7];
    const float* ebhh1    = (const float*)d_in[8];
    const float* dWih0    = (const float*)d_in[9];
    const float* dWhh0    = (const float*)d_in[10];
    const float* dbih0    = (const float*)d_in[11];
    const float* dbhh0    = (const float*)d_in[12];
    const float* dWih1    = (const float*)d_in[13];
    const float* dWhh1    = (const float*)d_in[14];
    const float* dbih1    = (const float*)d_in[15];
    const float* dbhh1    = (const float*)d_in[16];
    const float* out_W    = (const float*)d_in[17];
    const float* out_b    = (const float*)d_in[18];
    float* out = (float*)d_out;

    void* p;
    cudaGetSymbolAddress(&p, g_xp); float* xp = (float*)p;
    cudaGetSymbolAddress(&p, g_s0); float* s0 = (float*)p;
    cudaGetSymbolAddress(&p, g_s1); float* s1 = (float*)p;

    cudaFuncSetAttribute(lstm_rec, cudaFuncAttributeMaxDynamicSharedMemorySize, REC_SMEM);

    dim3 blk(256);
    dim3 gXP(G_ / 64, BT_ / 128);   // N=1024 tiles x M tiles
    dim3 gPR(I_ / 64, BT_ / 128);   // projection N=64

    // encoder layer 0 (K = I = 64)
    gemm_abt_bias<<<gXP, blk>>>(x, eWih0, ebih0, ebhh0, xp, BT_, G_, I_);
    lstm_rec<<<128, blk, REC_SMEM>>>(eWhh0, xp, s0);
    // encoder layer 1 (K = H)
    gemm_abt_bias<<<gXP, blk>>>(s0, eWih1, ebih1, ebhh1, xp, BT_, G_, H_);
    lstm_rec<<<128, blk, REC_SMEM>>>(eWhh1, xp, s1);
    // decoder layer 0
    gemm_abt_bias<<<gXP, blk>>>(s1, dWih0, dbih0, dbhh0, xp, BT_, G_, H_);
    lstm_rec<<<128, blk, REC_SMEM>>>(dWhh0, xp, s0);
    // decoder layer 1
    gemm_abt_bias<<<gXP, blk>>>(s0, dWih1, dbih1, dbhh1, xp, BT_, G_, H_);
    lstm_rec<<<128, blk, REC_SMEM>>>(dWhh1, xp, s1);
    // output projection (N = I = 64, K = H)
    gemm_abt_bias<<<gPR, blk>>>(s1, out_W, out_b, nullptr, out, BT_, I_, H_);
}

// round 3
// speedup vs baseline: 1.1985x; 1.1985x over previous
#include <cuda_runtime.h>
#include <cstdint>
#include <cstddef>

// Problem constants
#define B_  256
#define T_  512
#define I_  64
#define H_  256
#define G_  1024            // 4*H
#define BT_ (B_ * T_)       // 131072

// -------- scratch (device globals; no allocation allowed) --------
__device__ float g_xp[(size_t)BT_ * G_];   // gate pre-activations for current layer
__device__ float g_s0[(size_t)BT_ * H_];   // layer output sequence (ping)
__device__ float g_s1[(size_t)BT_ * H_];   // layer output sequence (pong)

// ---------------- packed f32x2 helpers (PTX-only path) ----------------
__device__ __forceinline__ unsigned long long pack2(float lo, float hi) {
    unsigned long long r;
    asm("mov.b64 %0, {%1, %2};" : "=l"(r)
        : "r"(__float_as_uint(lo)), "r"(__float_as_uint(hi)));
    return r;
}
__device__ __forceinline__ void fma2(unsigned long long& d,
                                     unsigned long long a, unsigned long long b) {
    asm("fma.rn.f32x2 %0, %1, %2, %0;" : "+l"(d) : "l"(a), "l"(b));
}
__device__ __forceinline__ float2 unpack2(unsigned long long v) {
    unsigned lo, hi;
    asm("mov.b64 {%0, %1}, %2;" : "=r"(lo), "=r"(hi) : "l"(v));
    return make_float2(__uint_as_float(lo), __uint_as_float(hi));
}

// =====================================================================
// GEMM: C[M,N] = A[M,K] * B[N,K]^T + bias1[N] (+ bias2[N])
// BM=128, BN=64, BK=16, 256 threads. f32x2 over M-pairs:
// A pairs natural from As[k][m] (ld.shared.v2.u64), B duplicated (4 packs/kk).
// =====================================================================
__global__ void __launch_bounds__(256, 2)
gemm_abt_bias(const float* __restrict__ A, const float* __restrict__ Bm,
              const float* __restrict__ bias1, const float* __restrict__ bias2,
              float* __restrict__ C, int M, int N, int K)
{
    __shared__ float As[16][128];
    __shared__ float Bs[16][64];

    const int tid = threadIdx.x;
    const int m0  = blockIdx.y * 128;
    const int n0  = blockIdx.x * 64;
    const int ty8 = (tid >> 4) * 8;   // row offset within tile (0..120)
    const int tx4 = (tid & 15) * 4;   // col offset within tile (0..60)

    unsigned long long acc2[4][4];    // [m-pair][n], each holds rows (ty8+2p, ty8+2p+1)
#pragma unroll
    for (int p = 0; p < 4; ++p)
#pragma unroll
        for (int j = 0; j < 4; ++j) acc2[p][j] = 0ULL;  // (0.0f, 0.0f)

    const int ntile = K >> 4;
    for (int kt = 0; kt < ntile; ++kt) {
        const int k0 = kt << 4;
#pragma unroll
        for (int r = 0; r < 2; ++r) {
            int idx = tid + (r << 8);
            int m = idx >> 2, kq = idx & 3;
            float4 v = *(const float4*)&A[(size_t)(m0 + m) * K + k0 + (kq << 2)];
            As[kq * 4 + 0][m] = v.x; As[kq * 4 + 1][m] = v.y;
            As[kq * 4 + 2][m] = v.z; As[kq * 4 + 3][m] = v.w;
        }
        {
            int n = tid >> 2, kq = tid & 3;
            float4 v = *(const float4*)&Bm[(size_t)(n0 + n) * K + k0 + (kq << 2)];
            Bs[kq * 4 + 0][n] = v.x; Bs[kq * 4 + 1][n] = v.y;
            Bs[kq * 4 + 2][n] = v.z; Bs[kq * 4 + 3][n] = v.w;
        }
        __syncthreads();

#pragma unroll
        for (int kk = 0; kk < 16; ++kk) {
            ulonglong2 a01 = *(const ulonglong2*)&As[kk][ty8];       // m pairs (0,1),(2,3)
            ulonglong2 a23 = *(const ulonglong2*)&As[kk][ty8 + 4];   // m pairs (4,5),(6,7)
            float4 bv = *(const float4*)&Bs[kk][tx4];
            unsigned long long am[4] = {a01.x, a01.y, a23.x, a23.y};
            float br[4] = {bv.x, bv.y, bv.z, bv.w};
#pragma unroll
            for (int j = 0; j < 4; ++j) {
                unsigned long long bp = pack2(br[j], br[j]);
#pragma unroll
                for (int p = 0; p < 4; ++p) fma2(acc2[p][j], am[p], bp);
            }
        }
        __syncthreads();
    }

    float bvv[4];
#pragma unroll
    for (int j = 0; j < 4; ++j) {
        float b = bias1[n0 + tx4 + j];
        if (bias2) b += bias2[n0 + tx4 + j];
        bvv[j] = b;
    }
#pragma unroll
    for (int p = 0; p < 4; ++p) {
        float4 o0, o1;
        float2 u0 = unpack2(acc2[p][0]);
        float2 u1 = unpack2(acc2[p][1]);
        float2 u2 = unpack2(acc2[p][2]);
        float2 u3 = unpack2(acc2[p][3]);
        o0.x = u0.x + bvv[0]; o0.y = u1.x + bvv[1]; o0.z = u2.x + bvv[2]; o0.w = u3.x + bvv[3];
        o1.x = u0.y + bvv[0]; o1.y = u1.y + bvv[1]; o1.z = u2.y + bvv[2]; o1.w = u3.y + bvv[3];
        *(float4*)&C[(size_t)(m0 + ty8 + 2 * p)     * N + n0 + tx4] = o0;
        *(float4*)&C[(size_t)(m0 + ty8 + 2 * p + 1) * N + n0 + tx4] = o1;
    }
}

// =====================================================================
// Recurrent LSTM scan v2: Whh register-resident, h broadcast from SMEM,
// fma.rn.f32x2 over k-pairs.
//   grid = 128 CTAs = 16 clusters x 8; cluster owns 16 batch rows.
//   CTA rank owns hidden cols [rank*32, rank*32+32) (gate rows
//   {g*256+rank*32+c}). Thread (warp w, lane l): row r = w*16+(l&15)
//   (r -> gate g=r>>5, col c=r&31), k-half s = l>>4.
//   rW[64] u64 = Whh[gr][s*128 .. s*128+128) packed as k-pairs.
//   hS[b][k] in SMEM, row pitch 260, k>=128 shifted +4 floats so the two
//   s-group broadcast addresses land in different banks.
//   Per step: stage h_{t-1} from global (coalesced LDG.128 + conflict-free
//   STS.128), dot (16 batch acc chains, 2 FMA2 per 4-k per batch),
//   unpack+hadd, shfl_xor(16) combine halves, exchange via ex[128][17],
//   gate math (2 (c,b) pairs/thread), write h, cluster barrier.
// =====================================================================
#define PH 260

__device__ __forceinline__ float fsig(float x) {
    x = fminf(fmaxf(x, -30.f), 30.f);
    return __fdividef(1.f, 1.f + __expf(-x));
}
__device__ __forceinline__ float ftanh_(float x) {
    x = fminf(fmaxf(x, -15.f), 15.f);
    float e = __expf(-2.f * x);
    return __fdividef(1.f - e, 1.f + e);
}

__global__ void __cluster_dims__(8, 1, 1) __launch_bounds__(256, 1)
lstm_rec(const float* __restrict__ Whh, const float* __restrict__ xpg,
         float* __restrict__ seq_out)
{
    __shared__ float hS[16 * PH];     // h_{t-1}: [batch][k], halves at +0 / +132
    __shared__ float ex[128 * 17];    // dot exchange: [row][batch]

    const int tid  = threadIdx.x;
    const int rank = blockIdx.x & 7;
    const int b0   = (blockIdx.x >> 3) * 16;

    const int w = tid >> 5, l = tid & 31;
    const int r = w * 16 + (l & 15);     // 0..127
    const int s = l >> 4;                // k-half
    const int gr = ((r >> 5) << 8) + (rank << 5) + (r & 31);  // global gate row

    // Whh slice into registers, packed as k-pairs
    unsigned long long rW[64];
#pragma unroll
    for (int jj = 0; jj < 32; ++jj) {
        ulonglong2 v = *(const ulonglong2*)&Whh[(size_t)gr * H_ + s * 128 + (jj << 2)];
        rW[2 * jj]     = v.x;
        rW[2 * jj + 1] = v.y;
    }

    // zero h buffer (t=0 state)
    for (int idx = tid; idx < 16 * PH; idx += 256) hS[idx] = 0.f;

    // gate-epilogue mapping (t-invariant): idx = b*32 + c
    int gb[2], gc[2];
#pragma unroll
    for (int u = 0; u < 2; ++u) {
        int idx = tid + (u << 8);
        gb[u] = idx >> 5; gc[u] = idx & 31;
    }
    float cst[2] = {0.f, 0.f};

    __syncthreads();

    for (int t = 0; t < T_; ++t) {
        // ---- stage h_{t-1} (coalesced along k) + prefetch xp ----
        float4 sg[4];
        if (t > 0) {
#pragma unroll
            for (int jj = 0; jj < 4; ++jj) {
                int f = tid + (jj << 8);
                int b = f >> 6, kq = f & 63;
                sg[jj] = *(const float4*)&seq_out[((size_t)(b0 + b) * T_ + (t - 1)) * H_ + (kq << 2)];
            }
        }
        float xv[2][4];
#pragma unroll
        for (int u = 0; u < 2; ++u)
#pragma unroll
            for (int g = 0; g < 4; ++g)
                xv[u][g] = __ldg(&xpg[((size_t)(b0 + gb[u]) * T_ + t) * G_ +
                                      (g << 8) + (rank << 5) + gc[u]]);
        if (t > 0) {
#pragma unroll
            for (int jj = 0; jj < 4; ++jj) {
                int f = tid + (jj << 8);
                int b = f >> 6, kq = f & 63, k0 = kq << 2;
                *(float4*)&hS[b * PH + k0 + ((k0 >= 128) ? 4 : 0)] = sg[jj];
            }
        }
        __syncthreads();

        // ---- dot: acc[b] accumulates (even-k, odd-k) partial pairs ----
        unsigned long long acc[16];
#pragma unroll
        for (int b = 0; b < 16; ++b) acc[b] = 0ULL;

        const float* hp = hS + s * 132;  // this thread's k-half base
#pragma unroll
        for (int jj = 0; jj < 32; ++jj) {
#pragma unroll
            for (int b = 0; b < 16; ++b) {
                ulonglong2 q = *(const ulonglong2*)&hp[b * PH + (jj << 2)];
                fma2(acc[b], rW[2 * jj],     q.x);
                fma2(acc[b], rW[2 * jj + 1], q.y);
            }
        }

        // ---- reduce: even/odd hadd, then combine k-halves via shuffle ----
        float d[16];
#pragma unroll
        for (int b = 0; b < 16; ++b) {
            float2 u = unpack2(acc[b]);
            d[b] = u.x + u.y;
        }
#pragma unroll
        for (int b = 0; b < 16; ++b)
            d[b] += __shfl_xor_sync(0xffffffffu, d[b], 16);
        if (s == 0) {
#pragma unroll
            for (int b = 0; b < 16; ++b) ex[r * 17 + b] = d[b];
        }
        __syncthreads();

        // ---- gates + state update + h write ----
#pragma unroll
        for (int u = 0; u < 2; ++u) {
            int b = gb[u], c = gc[u];
            float iv = ex[(c)      * 17 + b] + xv[u][0];
            float fv = ex[(32 + c) * 17 + b] + xv[u][1];
            float gv = ex[(64 + c) * 17 + b] + xv[u][2];
            float ov = ex[(96 + c) * 17 + b] + xv[u][3];
            float ig = fsig(iv), fg = fsig(fv), gg = ftanh_(gv), og = fsig(ov);
            cst[u] = fg * cst[u] + ig * gg;
            seq_out[((size_t)(b0 + b) * T_ + t) * H_ + (rank << 5) + c] = og * ftanh_(cst[u]);
        }

        // ---- cluster barrier: release h writes / acquire peers' ----
        asm volatile("barrier.cluster.arrive.aligned;\n\t"
                     "barrier.cluster.wait.aligned;\n\t" ::: "memory");
    }
}

// =====================================================================
// Launcher
// =====================================================================
extern "C" void kernel_launch(void* const* d_in, const int* in_sizes, int n_in,
                              void* d_out, int out_size)
{
    const float* x     = (const float*)d_in[0];
    const float* eWih0 = (const float*)d_in[1];
    const float* eWhh0 = (const float*)d_in[2];
    const float* ebih0 = (const float*)d_in[3];
    const float* ebhh0 = (const float*)d_in[4];
    const float* eWih1 = (const float*)d_in[5];
    const float* eWhh1 = (const float*)d_in[6];
    const float* ebih1 = (const float*)d_in[7];
    const float* ebhh1 = (const float*)d_in[8];
    const float* dWih0 = (const float*)d_in[9];
    const float* dWhh0 = (const float*)d_in[10];
    const float* dbih0 = (const float*)d_in[11];
    const float* dbhh0 = (const float*)d_in[12];
    const float* dWih1 = (const float*)d_in[13];
    const float* dWhh1 = (const float*)d_in[14];
    const float* dbih1 = (const float*)d_in[15];
    const float* dbhh1 = (const float*)d_in[16];
    const float* out_W = (const float*)d_in[17];
    const float* out_b = (const float*)d_in[18];
    float* out = (float*)d_out;

    void* p;
    cudaGetSymbolAddress(&p, g_xp); float* xp = (float*)p;
    cudaGetSymbolAddress(&p, g_s0); float* s0 = (float*)p;
    cudaGetSymbolAddress(&p, g_s1); float* s1 = (float*)p;

    dim3 blk(256);
    dim3 gXP(G_ / 64, BT_ / 128);   // N=1024 tiles x M tiles
    dim3 gPR(I_ / 64, BT_ / 128);   // projection N=64

    // encoder layer 0 (K = I = 64)
    gemm_abt_bias<<<gXP, blk>>>(x, eWih0, ebih0, ebhh0, xp, BT_, G_, I_);
    lstm_rec<<<128, blk>>>(eWhh0, xp, s0);
    // encoder layer 1 (K = H)
    gemm_abt_bias<<<gXP, blk>>>(s0, eWih1, ebih1, ebhh1, xp, BT_, G_, H_);
    lstm_rec<<<128, blk>>>(eWhh1, xp, s1);
    // decoder layer 0
    gemm_abt_bias<<<gXP, blk>>>(s1, dWih0, dbih0, dbhh0, xp, BT_, G_, H_);
    lstm_rec<<<128, blk>>>(dWhh0, xp, s0);
    // decoder layer 1
    gemm_abt_bias<<<gXP, blk>>>(s0, dWih1, dbih1, dbhh1, xp, BT_, G_, H_);
    lstm_rec<<<128, blk>>>(dWhh1, xp, s1);
    // output projection (N = I = 64, K = H)
    gemm_abt_bias<<<gPR, blk>>>(s1, out_W, out_b, nullptr, out, BT_, I_, H_);
}